// round 13
// baseline (speedup 1.0000x reference)
#include <cuda_runtime.h>
#include <cuda_bf16.h>
#include <cstdint>

#define BSZ 16
#define SSZ 4096
#define HSZ 1024
#define NTOK (BSZ * SSZ)

#define M_CTA 128
#define N_CHUNK 256
#define NCHUNK (HSZ / N_CHUNK)     // 4
#define NSPLIT 2                   // n-chunks split across 2 CTAs per tile
#define BK 32
#define NKSTAGE (HSZ / BK)         // 32 K-stages per chunk
#define NSTAGES_CTA ((NCHUNK / NSPLIT) * NKSTAGE)  // 64 stages per CTA
#define NBUF 3                     // smem buffer ring depth
#define LOOKAHEAD 2                // stages issued ahead

// B gmem tiled blocks (contiguous, pre-swizzled smem images)
#define B_BLK 32768                // 256 rows x 64B  (hi 16K | lo 16K)

// smem layout (bytes)
#define SOFF_SCORE 0               // float[128]
#define SOFF_KEY   512             // float[1024]
#define SOFF_BIAS  4608            // float[1024]
#define SOFF_MBAR  8640            // 3 x 8B mbarriers
#define SOFF_STAGE 9216
#define STG_F32 0                  // A fp32 staging: 128 rows x 128B = 16 KB
#define STG_AHI 16384              // A hi bf16: 128 rows x 64B = 8 KB
#define STG_ALO 24576              // A lo bf16: 8 KB
#define STG_B   32768              // B hi 16K | lo 16K (one gmem block)
#define STAGE_BYTES 65536
#define SMEM_TOTAL (SOFF_STAGE + NBUF * STAGE_BYTES)   // 205824

// output reduction tiling
#define SCHUNK 128                 // s positions per output block

// ---- scratch (no allocations allowed) ----
__device__ float g_scores_part[NSPLIT * NTOK];
__device__ float g_probs[NTOK];
// B: [chunk 4][kstage 32][32KB image]
__device__ __align__(1024) unsigned char g_b[(size_t)4 * 32 * B_BLK];   // 4 MB

// ---------------------------------------------------------------------------
__device__ __forceinline__ uint32_t s2u(const void* p) {
    return (uint32_t)__cvta_generic_to_shared(p);
}

__device__ __forceinline__ void cp16(uint32_t saddr, const void* gptr) {
    asm volatile("cp.async.cg.shared.global [%0], [%1], 16;"
                 :: "r"(saddr), "l"(gptr) : "memory");
}

#define LDMX4(r0, r1, r2, r3, addr) \
    asm volatile("ldmatrix.sync.aligned.m8n8.x4.shared.b16 {%0,%1,%2,%3}, [%4];" \
                 : "=r"(r0), "=r"(r1), "=r"(r2), "=r"(r3) : "r"(addr))

#define MMA16816(d, a, b) \
    asm volatile("mma.sync.aligned.m16n8k16.row.col.f32.bf16.bf16.f32 " \
                 "{%0,%1,%2,%3}, {%4,%5,%6,%7}, {%8,%9}, {%0,%1,%2,%3};" \
                 : "+f"((d)[0]), "+f"((d)[1]), "+f"((d)[2]), "+f"((d)[3]) \
                 : "r"((a)[0]), "r"((a)[1]), "r"((a)[2]), "r"((a)[3]), \
                   "r"((b)[0]), "r"((b)[1]))

__device__ __forceinline__ void mbar_init(uint32_t mbar, uint32_t cnt) {
    asm volatile("mbarrier.init.shared.b64 [%0], %1;" :: "r"(mbar), "r"(cnt) : "memory");
}

__device__ __forceinline__ void mbar_expect_tx(uint32_t mbar, uint32_t bytes) {
    asm volatile("mbarrier.arrive.expect_tx.shared.b64 _, [%0], %1;"
                 :: "r"(mbar), "r"(bytes) : "memory");
}

__device__ __forceinline__ void bulk_g2s(uint32_t sdst, const void* gsrc,
                                         uint32_t bytes, uint32_t mbar) {
    asm volatile("cp.async.bulk.shared::cluster.global.mbarrier::complete_tx::bytes "
                 "[%0], [%1], %2, [%3];"
                 :: "r"(sdst), "l"(gsrc), "r"(bytes), "r"(mbar) : "memory");
}

__device__ __forceinline__ void mbar_wait(uint32_t mbar, uint32_t phase) {
    uint32_t done;
    asm volatile(
        "{\n\t.reg .pred p;\n\t"
        "mbarrier.try_wait.parity.acquire.cta.shared::cta.b64 p, [%1], %2;\n\t"
        "selp.b32 %0, 1, 0, p;\n\t}"
        : "=r"(done) : "r"(mbar), "r"(phase) : "memory");
    if (!done) {
        asm volatile(
            "{\n\t.reg .pred P1;\n\t"
            "WAIT_LOOP_%=:\n\t"
            "mbarrier.try_wait.parity.acquire.cta.shared::cta.b64 P1, [%0], %1, 0x989680;\n\t"
            "@P1 bra.uni WAIT_DONE_%=;\n\t"
            "bra.uni WAIT_LOOP_%=;\n\t"
            "WAIT_DONE_%=:\n\t}"
            :: "r"(mbar), "r"(phase) : "memory");
    }
}

__device__ __forceinline__ float ftanh(float v) {
    float e = __expf(2.0f * v);
    return 1.0f - 2.0f / (e + 1.0f);
}

// ---------------------------------------------------------------------------
// Convert kernel for B (small: 4MB): fp32 -> bf16 hi/lo tiled images.
// Swizzle: 64B rows, 16B chunk c stored at c ^ ((r>>1)&3).
// ---------------------------------------------------------------------------
__global__ __launch_bounds__(256) void convert_b_kernel(const float* __restrict__ W)
{
    int id = blockIdx.x * 256 + threadIdx.x;      // (n, ks, c)
    int c  = id & 3;
    int ks = (id >> 2) & 31;
    int n  = id >> 7;
    const float* src = W + (size_t)n * HSZ + ks * 32 + c * 8;
    float4 v0 = *(const float4*)src;
    float4 v1 = *(const float4*)(src + 4);
    float a[8] = {v0.x, v0.y, v0.z, v0.w, v1.x, v1.y, v1.z, v1.w};

    uint4 hv, lv;
    __nv_bfloat16* hp = (__nv_bfloat16*)&hv;
    __nv_bfloat16* lp = (__nv_bfloat16*)&lv;
    #pragma unroll
    for (int j = 0; j < 8; j++) {
        hp[j] = __float2bfloat16(a[j]);
        lp[j] = __float2bfloat16(a[j] - __bfloat162float(hp[j]));
    }
    int r = n & 255;
    size_t off = ((size_t)(n >> 8) * 32 + ks) * B_BLK
               + (size_t)r * 64 + ((c ^ ((r >> 1) & 3)) << 4);
    *(uint4*)(g_b + off)         = hv;
    *(uint4*)(g_b + off + 16384) = lv;
}

// ---------------------------------------------------------------------------
// Kernel A: fused scores GEMM, bf16x3 split precision on mma.sync HMMA.
// A is loaded as RAW fp32 via cp.async (2x16B per thread per stage) and
// split to bf16 hi/lo IN-KERNEL each stage (smem->smem), overlapped with
// the MMA stream; B comes pre-converted via cp.async.bulk from g_b.
// This eliminates the serial convert_a pre-pass entirely (same smem bytes:
// fp32 tile 16KB == bf16 hi+lo 16KB). 3-deep ring, lookahead 2.
// ---------------------------------------------------------------------------
__global__ void __launch_bounds__(512, 1) gemm_scores_kernel(
    const float* __restrict__ x,
    const float* __restrict__ bias, const float* __restrict__ key)
{
    extern __shared__ char smem[];
    const uint32_t sbase = s2u(smem);
    const int tid = threadIdx.x;
    const int wid = tid >> 5;
    const int lid = tid & 31;
    const int wm  = wid & 3;          // warp m index (4)
    const int wn  = wid >> 2;         // warp n index (4)
    const int tile = blockIdx.x >> 1;
    const int half = blockIdx.x & 1;  // n-chunk pair: {0,1} or {2,3}
    const int t0  = tile * M_CTA;

    float* s_score = (float*)(smem + SOFF_SCORE);
    float* s_key   = (float*)(smem + SOFF_KEY);
    float* s_bias  = (float*)(smem + SOFF_BIAS);
    for (int i = tid; i < HSZ; i += 512) {
        s_key[i]  = key[i];
        s_bias[i] = bias[i];
    }
    if (tid < M_CTA) s_score[tid] = 0.0f;
    if (tid == 0) {
        #pragma unroll
        for (int i = 0; i < NBUF; i++) mbar_init(sbase + SOFF_MBAR + i * 8, 1);
    }
    __syncthreads();

    // per-thread A-load geometry: row r (0..127), 32B chunk c (0..3)
    const int ar = tid >> 2;
    const int ac = tid & 3;
    const float* a_src_base = x + (size_t)(t0 + ar) * HSZ + ac * 8;
    const uint32_t a_f32_off = (uint32_t)(ar * 128 + ac * 32);
    const uint32_t a_bf_off  = (uint32_t)(ar * 64 + ((ac ^ ((ar >> 1) & 3)) << 4));

    // prologue: issue stages 0..LOOKAHEAD-1
    #pragma unroll
    for (int s = 0; s < LOOKAHEAD; s++) {
        const uint32_t stg = sbase + SOFF_STAGE + (uint32_t)(s % NBUF) * STAGE_BYTES;
        if (tid == 0) {
            uint32_t mb = sbase + SOFF_MBAR + (s % NBUF) * 8;
            mbar_expect_tx(mb, B_BLK);
            bulk_g2s(stg + STG_B,
                     g_b + ((size_t)(half * 2 + (s >> 5)) * 32 + (s & 31)) * B_BLK,
                     B_BLK, mb);
        }
        cp16(stg + STG_F32 + a_f32_off,      a_src_base + (s & 31) * 32);
        cp16(stg + STG_F32 + a_f32_off + 16, a_src_base + (s & 31) * 32 + 4);
        asm volatile("cp.async.commit_group;" ::: "memory");
    }

    // ldmatrix lane geometry
    const int g  = lid >> 3;          // quad-group 0..3
    const int r8 = lid & 7;
    const int a_row  = wm * 32 + (g & 1) * 8 + r8;   // + i*16
    const int a_kh   = g >> 1;                       // k8-half
    const int b_rowb = wn * 64 + (g >> 1) * 8 + r8;  // + nh*32 + p*16
    const int b_kh   = g & 1;
    const int a_xm   = (a_row  >> 1) & 3;            // xor mask (invariant to +16/+32)
    const int b_xm   = (b_rowb >> 1) & 3;

    float acc[2][8][4];
    float score_p[2][2];

    for (int gs = 0; gs < NSTAGES_CTA; gs++) {
        const int ks  = gs & 31;
        const int buf = gs % NBUF;
        const uint32_t stg = sbase + SOFF_STAGE + (uint32_t)buf * STAGE_BYTES;

        if (ks == 0) {
            #pragma unroll
            for (int i = 0; i < 2; i++)
                #pragma unroll
                for (int j = 0; j < 8; j++)
                    #pragma unroll
                    for (int c = 0; c < 4; c++) acc[i][j][c] = 0.0f;
        }

        // wait A fp32 (own thread's cp.async; in-order groups => wait_group 1
        // leaves at most the newest group pending) and B bulk.
        asm volatile("cp.async.wait_group 1;" ::: "memory");
        mbar_wait(sbase + SOFF_MBAR + buf * 8, (gs / NBUF) & 1);

        // convert this stage's A tile: fp32 smem -> bf16 hi/lo smem
        {
            const float* f = (const float*)(smem + SOFF_STAGE
                             + (size_t)buf * STAGE_BYTES + STG_F32 + a_f32_off);
            float4 v0 = ((const float4*)f)[0];
            float4 v1 = ((const float4*)f)[1];
            float a[8] = {v0.x, v0.y, v0.z, v0.w, v1.x, v1.y, v1.z, v1.w};
            uint4 hv, lv;
            __nv_bfloat16* hp = (__nv_bfloat16*)&hv;
            __nv_bfloat16* lp = (__nv_bfloat16*)&lv;
            #pragma unroll
            for (int j = 0; j < 8; j++) {
                hp[j] = __float2bfloat16(a[j]);
                lp[j] = __float2bfloat16(a[j] - __bfloat162float(hp[j]));
            }
            char* dst = smem + SOFF_STAGE + (size_t)buf * STAGE_BYTES + STG_AHI
                      + a_bf_off;
            *(uint4*)dst          = hv;
            *(uint4*)(dst + 8192) = lv;
        }
        __syncthreads();   // conversions visible; prior stage fully consumed

        // issue stage gs+LOOKAHEAD into the buffer freed at stage gs-1
        {
            const int s = gs + LOOKAHEAD;
            if (s < NSTAGES_CTA) {
                const uint32_t nstg = sbase + SOFF_STAGE
                                    + (uint32_t)(s % NBUF) * STAGE_BYTES;
                if (tid == 0) {
                    uint32_t mb = sbase + SOFF_MBAR + (s % NBUF) * 8;
                    mbar_expect_tx(mb, B_BLK);
                    bulk_g2s(nstg + STG_B,
                             g_b + ((size_t)(half * 2 + (s >> 5)) * 32
                                    + (s & 31)) * B_BLK,
                             B_BLK, mb);
                }
                cp16(nstg + STG_F32 + a_f32_off,      a_src_base + (s & 31) * 32);
                cp16(nstg + STG_F32 + a_f32_off + 16, a_src_base + (s & 31) * 32 + 4);
            }
            asm volatile("cp.async.commit_group;" ::: "memory");
        }

        #pragma unroll
        for (int k16 = 0; k16 < 2; k16++) {
            uint32_t ah[2][4], al[2][4];
            const uint32_t a_csw = (uint32_t)(((k16 * 2 + a_kh) ^ a_xm) << 4);
            #pragma unroll
            for (int i = 0; i < 2; i++) {
                uint32_t off = (uint32_t)((a_row + i * 16) << 6) + a_csw;
                LDMX4(ah[i][0], ah[i][1], ah[i][2], ah[i][3], stg + STG_AHI + off);
                LDMX4(al[i][0], al[i][1], al[i][2], al[i][3], stg + STG_ALO + off);
            }
            const uint32_t b_csw = (uint32_t)(((k16 * 2 + b_kh) ^ b_xm) << 4);
            #pragma unroll
            for (int nh = 0; nh < 2; nh++) {
                uint32_t bh[4][2], bl[4][2];
                #pragma unroll
                for (int p = 0; p < 2; p++) {
                    uint32_t off = (uint32_t)((b_rowb + nh * 32 + p * 16) << 6) + b_csw;
                    LDMX4(bh[2*p][0], bh[2*p][1], bh[2*p+1][0], bh[2*p+1][1],
                          stg + STG_B + off);
                    LDMX4(bl[2*p][0], bl[2*p][1], bl[2*p+1][0], bl[2*p+1][1],
                          stg + STG_B + 16384 + off);
                }
                #pragma unroll
                for (int i = 0; i < 2; i++)
                    #pragma unroll
                    for (int j = 0; j < 4; j++) {
                        MMA16816(acc[i][nh * 4 + j], ah[i], bh[j]);  // hi*hi
                        MMA16816(acc[i][nh * 4 + j], ah[i], bl[j]);  // hi*lo
                        MMA16816(acc[i][nh * 4 + j], al[i], bh[j]);  // lo*hi
                    }
            }
        }

        if (ks == 31) {
            // epilogue for this n-chunk: tanh(acc+bias)*key -> score partials
            const int n0 = (half * 2 + (gs >> 5)) * N_CHUNK;
            #pragma unroll
            for (int i = 0; i < 2; i++)
                #pragma unroll
                for (int mh = 0; mh < 2; mh++) score_p[i][mh] = 0.0f;

            #pragma unroll
            for (int i = 0; i < 2; i++)
                #pragma unroll
                for (int j = 0; j < 8; j++)
                    #pragma unroll
                    for (int c = 0; c < 4; c++) {
                        int n = n0 + wn * 64 + j * 8 + (lid & 3) * 2 + (c & 1);
                        float v = ftanh(acc[i][j][c] + s_bias[n]) * s_key[n];
                        score_p[i][c >> 1] += v;
                    }

            #pragma unroll
            for (int i = 0; i < 2; i++)
                #pragma unroll
                for (int mh = 0; mh < 2; mh++) {
                    float v = score_p[i][mh];
                    v += __shfl_xor_sync(0xffffffffu, v, 1);
                    v += __shfl_xor_sync(0xffffffffu, v, 2);
                    if ((lid & 3) == 0) {
                        int m = wm * 32 + i * 16 + mh * 8 + (lid >> 2);
                        atomicAdd(&s_score[m], v);
                    }
                }
        }
    }

    __syncthreads();
    if (tid < M_CTA) g_scores_part[half * NTOK + t0 + tid] = s_score[tid];
}

// ---------------------------------------------------------------------------
// Kernel B1: per-batch masked softmax over summed partial scores -> probs.
// ---------------------------------------------------------------------------
__global__ __launch_bounds__(256) void softmax_kernel(const int* __restrict__ lengths)
{
    __shared__ float red[256];
    const int b = blockIdx.x;
    const int len = lengths[b];
    const float* sc0 = g_scores_part + b * SSZ;
    const float* sc1 = g_scores_part + NTOK + b * SSZ;
    const int tid = threadIdx.x;

    float m = -1e30f;
    for (int s = tid; s < len; s += 256) m = fmaxf(m, sc0[s] + sc1[s]);
    red[tid] = m;
    __syncthreads();
    for (int o = 128; o > 0; o >>= 1) {
        if (tid < o) red[tid] = fmaxf(red[tid], red[tid + o]);
        __syncthreads();
    }
    m = red[0];
    __syncthreads();

    float sum = 0.f;
    for (int s = tid; s < len; s += 256) sum += expf(sc0[s] + sc1[s] - m);
    red[tid] = sum;
    __syncthreads();
    for (int o = 128; o > 0; o >>= 1) {
        if (tid < o) red[tid] += red[tid + o];
        __syncthreads();
    }
    const float inv = 1.0f / red[0];

    for (int s = tid; s < SSZ; s += 256)
        g_probs[b * SSZ + s] = (s < len) ? expf(sc0[s] + sc1[s] - m) * inv : 0.f;
}

// ---------------------------------------------------------------------------
// Kernel B2a: zero the output (harness poisons it to 0xAA).
// ---------------------------------------------------------------------------
__global__ __launch_bounds__(256) void output_init_kernel(float* __restrict__ out)
{
    out[blockIdx.x * 256 + threadIdx.x] = 0.0f;
}

// ---------------------------------------------------------------------------
// Kernel B2b: out[b,h] += sum_{s in chunk, s<len} probs[b,s] * x[b,s,h]
// ---------------------------------------------------------------------------
__global__ __launch_bounds__(256) void output_kernel(
    const float* __restrict__ x, const int* __restrict__ lengths,
    float* __restrict__ out)
{
    const int b  = blockIdx.y;
    const int s0 = blockIdx.x * SCHUNK;
    const int len = lengths[b];
    if (s0 >= len) return;
    const int ns = min(SCHUNK, len - s0);

    const int h4 = threadIdx.x * 4;
    const float4* xb = (const float4*)(x + ((size_t)b * SSZ + s0) * HSZ + h4);
    const float* pb = g_probs + b * SSZ + s0;

    float a0 = 0.f, a1 = 0.f, a2 = 0.f, a3 = 0.f;
    for (int s = 0; s < ns; s++) {
        float p = pb[s];
        float4 v = xb[(size_t)s * (HSZ / 4)];
        a0 += p * v.x;
        a1 += p * v.y;
        a2 += p * v.z;
        a3 += p * v.w;
    }
    float* o = out + b * HSZ + h4;
    atomicAdd(o + 0, a0);
    atomicAdd(o + 1, a1);
    atomicAdd(o + 2, a2);
    atomicAdd(o + 3, a3);
}

// ---------------------------------------------------------------------------
extern "C" void kernel_launch(void* const* d_in, const int* in_sizes, int n_in,
                              void* d_out, int out_size)
{
    const float* x       = (const float*)d_in[0];
    const int*   lengths = (const int*)  d_in[1];
    const float* W       = (const float*)d_in[2];
    const float* bias    = (const float*)d_in[3];
    const float* key     = (const float*)d_in[4];
    float* out = (float*)d_out;

    cudaFuncSetAttribute(gemm_scores_kernel,
                         cudaFuncAttributeMaxDynamicSharedMemorySize, SMEM_TOTAL);

    convert_b_kernel<<<(HSZ * 32 * 4) / 256, 256>>>(W);

    gemm_scores_kernel<<<(NTOK / M_CTA) * NSPLIT, 512, SMEM_TOTAL>>>(x, bias, key);
    softmax_kernel<<<BSZ, 256>>>(lengths);
    output_init_kernel<<<(BSZ * HSZ) / 256, 256>>>(out);
    output_kernel<<<dim3(SSZ / SCHUNK, BSZ), 256>>>(x, lengths, out);
}

// round 14
// speedup vs baseline: 1.1245x; 1.1245x over previous
#include <cuda_runtime.h>
#include <cuda_bf16.h>
#include <cstdint>

#define BSZ 16
#define SSZ 4096
#define HSZ 1024
#define NTOK (BSZ * SSZ)

#define M_CTA 128
#define N_CHUNK 256
#define NCHUNK (HSZ / N_CHUNK)     // 4
#define NSPLIT 2                   // n-chunks split across 2 CTAs per tile
// one pipeline stage now covers 64 K (two 32-K blocks fetched contiguously)
#define NSTAGES_CTA 32             // (NCHUNK/NSPLIT) chunks * 16 double-stages
#define NBUF 2                     // smem buffer ring depth

// gmem tiled blocks (contiguous, pre-swizzled smem images; 32-K granularity)
#define A_BLK 16384                // 128 rows x 64B  (hi 8K | lo 8K)
#define B_BLK 32768                // 256 rows x 64B  (hi 16K | lo 16K)

// smem layout (bytes)
#define SOFF_SCORE 0               // float[128]
#define SOFF_KEY   512             // float[1024]
#define SOFF_BIAS  4608            // float[1024]
#define SOFF_MBAR  8640            // 2 x 8B mbarriers
#define SOFF_STAGE 9216
#define STG_A   0                  // two A blocks: [hi0|lo0|hi1|lo1] = 32 KB
#define STG_B   32768              // two B blocks: [hi0|lo0|hi1|lo1] = 64 KB
#define STAGE_BYTES 98304
#define SMEM_TOTAL (SOFF_STAGE + NBUF * STAGE_BYTES)   // 205824

// output reduction tiling
#define SCHUNK 128                 // s positions per output block

// ---- scratch (no allocations allowed) ----
__device__ float g_scores_part[NSPLIT * NTOK];
__device__ float g_probs[NTOK];
// A: [tile 512][kstage 32][16KB image]   B: [chunk 4][kstage 32][32KB image]
__device__ __align__(1024) unsigned char g_a[(size_t)512 * 32 * A_BLK]; // 268 MB
__device__ __align__(1024) unsigned char g_b[(size_t)4 * 32 * B_BLK];   // 4 MB

// ---------------------------------------------------------------------------
__device__ __forceinline__ uint32_t s2u(const void* p) {
    return (uint32_t)__cvta_generic_to_shared(p);
}

#define LDMX4(r0, r1, r2, r3, addr) \
    asm volatile("ldmatrix.sync.aligned.m8n8.x4.shared.b16 {%0,%1,%2,%3}, [%4];" \
                 : "=r"(r0), "=r"(r1), "=r"(r2), "=r"(r3) : "r"(addr))

#define MMA16816(d, a, b) \
    asm volatile("mma.sync.aligned.m16n8k16.row.col.f32.bf16.bf16.f32 " \
                 "{%0,%1,%2,%3}, {%4,%5,%6,%7}, {%8,%9}, {%0,%1,%2,%3};" \
                 : "+f"((d)[0]), "+f"((d)[1]), "+f"((d)[2]), "+f"((d)[3]) \
                 : "r"((a)[0]), "r"((a)[1]), "r"((a)[2]), "r"((a)[3]), \
                   "r"((b)[0]), "r"((b)[1]))

__device__ __forceinline__ void mbar_init(uint32_t mbar, uint32_t cnt) {
    asm volatile("mbarrier.init.shared.b64 [%0], %1;" :: "r"(mbar), "r"(cnt) : "memory");
}

__device__ __forceinline__ void mbar_expect_tx(uint32_t mbar, uint32_t bytes) {
    asm volatile("mbarrier.arrive.expect_tx.shared.b64 _, [%0], %1;"
                 :: "r"(mbar), "r"(bytes) : "memory");
}

__device__ __forceinline__ void bulk_g2s(uint32_t sdst, const void* gsrc,
                                         uint32_t bytes, uint32_t mbar) {
    asm volatile("cp.async.bulk.shared::cluster.global.mbarrier::complete_tx::bytes "
                 "[%0], [%1], %2, [%3];"
                 :: "r"(sdst), "l"(gsrc), "r"(bytes), "r"(mbar) : "memory");
}

__device__ __forceinline__ void mbar_wait(uint32_t mbar, uint32_t phase) {
    uint32_t done;
    asm volatile(
        "{\n\t.reg .pred p;\n\t"
        "mbarrier.try_wait.parity.acquire.cta.shared::cta.b64 p, [%1], %2;\n\t"
        "selp.b32 %0, 1, 0, p;\n\t}"
        : "=r"(done) : "r"(mbar), "r"(phase) : "memory");
    if (!done) {
        asm volatile(
            "{\n\t.reg .pred P1;\n\t"
            "WAIT_LOOP_%=:\n\t"
            "mbarrier.try_wait.parity.acquire.cta.shared::cta.b64 P1, [%0], %1, 0x989680;\n\t"
            "@P1 bra.uni WAIT_DONE_%=;\n\t"
            "bra.uni WAIT_LOOP_%=;\n\t"
            "WAIT_DONE_%=:\n\t}"
            :: "r"(mbar), "r"(phase) : "memory");
    }
}

__device__ __forceinline__ float ftanh(float v) {
    float e = __expf(2.0f * v);
    return 1.0f - 2.0f / (e + 1.0f);
}

// ---------------------------------------------------------------------------
// Convert kernels: fp32 -> bf16 hi/lo, written as pre-tiled pre-swizzled
// smem images. Swizzle: 64B rows, 16B chunk c stored at c ^ ((r>>1)&3).
// ---------------------------------------------------------------------------
__global__ __launch_bounds__(256) void convert_a_kernel(const float* __restrict__ x)
{
    int id = blockIdx.x * 256 + threadIdx.x;      // (t, ks, c)
    int c  = id & 3;
    int ks = (id >> 2) & 31;
    int t  = id >> 7;
    const float* src = x + (size_t)t * HSZ + ks * 32 + c * 8;
    float4 v0 = *(const float4*)src;
    float4 v1 = *(const float4*)(src + 4);
    float a[8] = {v0.x, v0.y, v0.z, v0.w, v1.x, v1.y, v1.z, v1.w};

    uint4 hv, lv;
    __nv_bfloat16* hp = (__nv_bfloat16*)&hv;
    __nv_bfloat16* lp = (__nv_bfloat16*)&lv;
    #pragma unroll
    for (int j = 0; j < 8; j++) {
        hp[j] = __float2bfloat16(a[j]);
        lp[j] = __float2bfloat16(a[j] - __bfloat162float(hp[j]));
    }
    int r = t & 127;
    size_t off = ((size_t)(t >> 7) * 32 + ks) * A_BLK
               + (size_t)r * 64 + ((c ^ ((r >> 1) & 3)) << 4);
    *(uint4*)(g_a + off)        = hv;
    *(uint4*)(g_a + off + 8192) = lv;
}

__global__ __launch_bounds__(256) void convert_b_kernel(const float* __restrict__ W)
{
    int id = blockIdx.x * 256 + threadIdx.x;      // (n, ks, c)
    int c  = id & 3;
    int ks = (id >> 2) & 31;
    int n  = id >> 7;
    const float* src = W + (size_t)n * HSZ + ks * 32 + c * 8;
    float4 v0 = *(const float4*)src;
    float4 v1 = *(const float4*)(src + 4);
    float a[8] = {v0.x, v0.y, v0.z, v0.w, v1.x, v1.y, v1.z, v1.w};

    uint4 hv, lv;
    __nv_bfloat16* hp = (__nv_bfloat16*)&hv;
    __nv_bfloat16* lp = (__nv_bfloat16*)&lv;
    #pragma unroll
    for (int j = 0; j < 8; j++) {
        hp[j] = __float2bfloat16(a[j]);
        lp[j] = __float2bfloat16(a[j] - __bfloat162float(hp[j]));
    }
    int r = n & 255;
    size_t off = ((size_t)(n >> 8) * 32 + ks) * B_BLK
               + (size_t)r * 64 + ((c ^ ((r >> 1) & 3)) << 4);
    *(uint4*)(g_b + off)         = hv;
    *(uint4*)(g_b + off + 16384) = lv;
}

// ---------------------------------------------------------------------------
// Kernel A: fused scores GEMM, bf16x3 split precision on mma.sync HMMA.
// Double-K stages: each pipeline stage fetches TWO contiguous 32-K blocks
// (one 32KB A bulk + one 64KB B bulk) and computes 64 K before the next
// mbar_wait/__syncthreads — halving per-stage sync overhead vs BK=32.
// NBUF=2 x 96KB ring; N-split across 2 CTAs per tile.
// ---------------------------------------------------------------------------
__global__ void __launch_bounds__(512, 1) gemm_scores_kernel(
    const float* __restrict__ bias, const float* __restrict__ key)
{
    extern __shared__ char smem[];
    const uint32_t sbase = s2u(smem);
    const int tid = threadIdx.x;
    const int wid = tid >> 5;
    const int lid = tid & 31;
    const int wm  = wid & 3;          // warp m index (4)
    const int wn  = wid >> 2;         // warp n index (4)
    const int tile = blockIdx.x >> 1;
    const int half = blockIdx.x & 1;  // n-chunk pair: {0,1} or {2,3}
    const int t0  = tile * M_CTA;

    float* s_score = (float*)(smem + SOFF_SCORE);
    float* s_key   = (float*)(smem + SOFF_KEY);
    float* s_bias  = (float*)(smem + SOFF_BIAS);
    for (int i = tid; i < HSZ; i += 512) {
        s_key[i]  = key[i];
        s_bias[i] = bias[i];
    }
    if (tid < M_CTA) s_score[tid] = 0.0f;
    if (tid == 0) {
        #pragma unroll
        for (int i = 0; i < NBUF; i++) mbar_init(sbase + SOFF_MBAR + i * 8, 1);
    }
    __syncthreads();

    // prologue: stages 0 and 1 (both buffers free at start)
    if (tid == 0) {
        #pragma unroll
        for (int s = 0; s < 2; s++) {
            const int kp = (s & 15) * 2;          // first 32-K block of pair
            const int ch = half * 2 + (s >> 4);
            uint32_t mb  = sbase + SOFF_MBAR + (s & 1) * 8;
            uint32_t stg = sbase + SOFF_STAGE + (uint32_t)(s & 1) * STAGE_BYTES;
            mbar_expect_tx(mb, STAGE_BYTES);
            bulk_g2s(stg + STG_A, g_a + ((size_t)tile * 32 + kp) * A_BLK,
                     2 * A_BLK, mb);
            bulk_g2s(stg + STG_B, g_b + ((size_t)ch * 32 + kp) * B_BLK,
                     2 * B_BLK, mb);
        }
    }

    // ldmatrix lane geometry
    const int g  = lid >> 3;          // quad-group 0..3
    const int r8 = lid & 7;
    const int a_row  = wm * 32 + (g & 1) * 8 + r8;   // + i*16
    const int a_kh   = g >> 1;                       // k8-half
    const int b_rowb = wn * 64 + (g >> 1) * 8 + r8;  // + nh*32 + p*16
    const int b_kh   = g & 1;
    const int a_xm   = (a_row  >> 1) & 3;            // xor mask (invariant to +16/+32)
    const int b_xm   = (b_rowb >> 1) & 3;

    float acc[2][8][4];
    float score_p[2][2];

    for (int gs = 0; gs < NSTAGES_CTA; gs++) {
        const int buf = gs & 1;
        const uint32_t stg = sbase + SOFF_STAGE + (uint32_t)buf * STAGE_BYTES;

        if ((gs & 15) == 0) {
            #pragma unroll
            for (int i = 0; i < 2; i++)
                #pragma unroll
                for (int j = 0; j < 8; j++)
                    #pragma unroll
                    for (int c = 0; c < 4; c++) acc[i][j][c] = 0.0f;
        }

        mbar_wait(sbase + SOFF_MBAR + buf * 8, (gs >> 1) & 1);

        // compute 64 K: two 32-K sub-blocks, each with two k16 halves
        #pragma unroll
        for (int ss = 0; ss < 2; ss++) {
            const uint32_t a_base = stg + STG_A + (uint32_t)ss * 16384;
            const uint32_t b_base = stg + STG_B + (uint32_t)ss * 32768;
            #pragma unroll
            for (int k16 = 0; k16 < 2; k16++) {
                uint32_t ah[2][4], al[2][4];
                const uint32_t a_csw = (uint32_t)(((k16 * 2 + a_kh) ^ a_xm) << 4);
                #pragma unroll
                for (int i = 0; i < 2; i++) {
                    uint32_t off = (uint32_t)((a_row + i * 16) << 6) + a_csw;
                    LDMX4(ah[i][0], ah[i][1], ah[i][2], ah[i][3], a_base + off);
                    LDMX4(al[i][0], al[i][1], al[i][2], al[i][3], a_base + 8192 + off);
                }
                const uint32_t b_csw = (uint32_t)(((k16 * 2 + b_kh) ^ b_xm) << 4);
                #pragma unroll
                for (int nh = 0; nh < 2; nh++) {
                    uint32_t bh[4][2], bl[4][2];
                    #pragma unroll
                    for (int p = 0; p < 2; p++) {
                        uint32_t off = (uint32_t)((b_rowb + nh * 32 + p * 16) << 6)
                                     + b_csw;
                        LDMX4(bh[2*p][0], bh[2*p][1], bh[2*p+1][0], bh[2*p+1][1],
                              b_base + off);
                        LDMX4(bl[2*p][0], bl[2*p][1], bl[2*p+1][0], bl[2*p+1][1],
                              b_base + 16384 + off);
                    }
                    #pragma unroll
                    for (int i = 0; i < 2; i++)
                        #pragma unroll
                        for (int j = 0; j < 4; j++) {
                            MMA16816(acc[i][nh * 4 + j], ah[i], bh[j]);  // hi*hi
                            MMA16816(acc[i][nh * 4 + j], ah[i], bl[j]);  // hi*lo
                            MMA16816(acc[i][nh * 4 + j], al[i], bh[j]);  // lo*hi
                        }
                }
            }
        }

        if ((gs & 15) == 15) {
            // epilogue for this n-chunk: tanh(acc+bias)*key -> score partials
            const int n0 = (half * 2 + (gs >> 4)) * N_CHUNK;
            #pragma unroll
            for (int i = 0; i < 2; i++)
                #pragma unroll
                for (int mh = 0; mh < 2; mh++) score_p[i][mh] = 0.0f;

            #pragma unroll
            for (int i = 0; i < 2; i++)
                #pragma unroll
                for (int j = 0; j < 8; j++)
                    #pragma unroll
                    for (int c = 0; c < 4; c++) {
                        int n = n0 + wn * 64 + j * 8 + (lid & 3) * 2 + (c & 1);
                        float v = ftanh(acc[i][j][c] + s_bias[n]) * s_key[n];
                        score_p[i][c >> 1] += v;
                    }

            #pragma unroll
            for (int i = 0; i < 2; i++)
                #pragma unroll
                for (int mh = 0; mh < 2; mh++) {
                    float v = score_p[i][mh];
                    v += __shfl_xor_sync(0xffffffffu, v, 1);
                    v += __shfl_xor_sync(0xffffffffu, v, 2);
                    if ((lid & 3) == 0) {
                        int m = wm * 32 + i * 16 + mh * 8 + (lid >> 2);
                        atomicAdd(&s_score[m], v);
                    }
                }
        }

        __syncthreads();   // all warps done with this buffer -> reusable

        // issue stage gs+2 into the buffer just freed
        if (tid == 0 && gs + 2 < NSTAGES_CTA) {
            const int s  = gs + 2;
            const int kp = (s & 15) * 2;
            const int ch = half * 2 + (s >> 4);
            uint32_t mb = sbase + SOFF_MBAR + buf * 8;
            mbar_expect_tx(mb, STAGE_BYTES);
            bulk_g2s(stg + STG_A, g_a + ((size_t)tile * 32 + kp) * A_BLK,
                     2 * A_BLK, mb);
            bulk_g2s(stg + STG_B, g_b + ((size_t)ch * 32 + kp) * B_BLK,
                     2 * B_BLK, mb);
        }
    }

    __syncthreads();
    if (tid < M_CTA) g_scores_part[half * NTOK + t0 + tid] = s_score[tid];
}

// ---------------------------------------------------------------------------
// Kernel B1: per-batch masked softmax over summed partial scores -> probs.
// ---------------------------------------------------------------------------
__global__ __launch_bounds__(256) void softmax_kernel(const int* __restrict__ lengths)
{
    __shared__ float red[256];
    const int b = blockIdx.x;
    const int len = lengths[b];
    const float* sc0 = g_scores_part + b * SSZ;
    const float* sc1 = g_scores_part + NTOK + b * SSZ;
    const int tid = threadIdx.x;

    float m = -1e30f;
    for (int s = tid; s < len; s += 256) m = fmaxf(m, sc0[s] + sc1[s]);
    red[tid] = m;
    __syncthreads();
    for (int o = 128; o > 0; o >>= 1) {
        if (tid < o) red[tid] = fmaxf(red[tid], red[tid + o]);
        __syncthreads();
    }
    m = red[0];
    __syncthreads();

    float sum = 0.f;
    for (int s = tid; s < len; s += 256) sum += expf(sc0[s] + sc1[s] - m);
    red[tid] = sum;
    __syncthreads();
    for (int o = 128; o > 0; o >>= 1) {
        if (tid < o) red[tid] += red[tid + o];
        __syncthreads();
    }
    const float inv = 1.0f / red[0];

    for (int s = tid; s < SSZ; s += 256)
        g_probs[b * SSZ + s] = (s < len) ? expf(sc0[s] + sc1[s] - m) * inv : 0.f;
}

// ---------------------------------------------------------------------------
// Kernel B2a: zero the output (harness poisons it to 0xAA).
// ---------------------------------------------------------------------------
__global__ __launch_bounds__(256) void output_init_kernel(float* __restrict__ out)
{
    out[blockIdx.x * 256 + threadIdx.x] = 0.0f;
}

// ---------------------------------------------------------------------------
// Kernel B2b: out[b,h] += sum_{s in chunk, s<len} probs[b,s] * x[b,s,h]
// ---------------------------------------------------------------------------
__global__ __launch_bounds__(256) void output_kernel(
    const float* __restrict__ x, const int* __restrict__ lengths,
    float* __restrict__ out)
{
    const int b  = blockIdx.y;
    const int s0 = blockIdx.x * SCHUNK;
    const int len = lengths[b];
    if (s0 >= len) return;
    const int ns = min(SCHUNK, len - s0);

    const int h4 = threadIdx.x * 4;
    const float4* xb = (const float4*)(x + ((size_t)b * SSZ + s0) * HSZ + h4);
    const float* pb = g_probs + b * SSZ + s0;

    float a0 = 0.f, a1 = 0.f, a2 = 0.f, a3 = 0.f;
    for (int s = 0; s < ns; s++) {
        float p = pb[s];
        float4 v = xb[(size_t)s * (HSZ / 4)];
        a0 += p * v.x;
        a1 += p * v.y;
        a2 += p * v.z;
        a3 += p * v.w;
    }
    float* o = out + b * HSZ + h4;
    atomicAdd(o + 0, a0);
    atomicAdd(o + 1, a1);
    atomicAdd(o + 2, a2);
    atomicAdd(o + 3, a3);
}

// ---------------------------------------------------------------------------
extern "C" void kernel_launch(void* const* d_in, const int* in_sizes, int n_in,
                              void* d_out, int out_size)
{
    const float* x       = (const float*)d_in[0];
    const int*   lengths = (const int*)  d_in[1];
    const float* W       = (const float*)d_in[2];
    const float* bias    = (const float*)d_in[3];
    const float* key     = (const float*)d_in[4];
    float* out = (float*)d_out;

    cudaFuncSetAttribute(gemm_scores_kernel,
                         cudaFuncAttributeMaxDynamicSharedMemorySize, SMEM_TOTAL);

    convert_a_kernel<<<(NTOK * 32 * 4) / 256, 256>>>(x);
    convert_b_kernel<<<(HSZ * 32 * 4) / 256, 256>>>(W);

    gemm_scores_kernel<<<(NTOK / M_CTA) * NSPLIT, 512, SMEM_TOTAL>>>(bias, key);
    softmax_kernel<<<BSZ, 256>>>(lengths);
    output_init_kernel<<<(BSZ * HSZ) / 256, 256>>>(out);
    output_kernel<<<dim3(SSZ / SCHUNK, BSZ), 256>>>(x, lengths, out);
}